// round 1
// baseline (speedup 1.0000x reference)
#include <cuda_runtime.h>
#include <math.h>

#define NTHREADS 256
#define NENS 8
#define HID 64

// Shared-memory float offsets
#define OFF_W1 0                 // 8*6*64  = 3072
#define OFF_B1 3072              // 8*64    = 512
#define OFF_W2 3584              // 8*64*64 = 32768
#define OFF_B2 36352             // 512
#define OFF_W3 36864             // 512
#define OFF_B3 37376             // 8
#define SMEM_FLOATS 37384
#define SMEM_BYTES (SMEM_FLOATS * 4)

// Relativistic shock jump (Taub adiabat), gamma = 5/3.
// Returns rhoC, hC, vstar, Vs (epsC/Ws unused downstream).
__device__ __forceinline__ void get_vel_shock(
    float pC, float rho, float p, float v, float sign,
    float& rhoC, float& hC, float& vstar, float& Vs)
{
    float h  = 1.0f + 2.5f * p / rho;                 // gamma/(gamma-1) = 2.5
    float W  = 1.0f / sqrtf(1.0f - v * v);
    float dp = p - pC;
    float A  = 1.0f + 0.4f * dp / pC;                 // (gamma-1)/gamma = 0.4
    float B  = -0.4f * dp / pC;
    float C  = h * dp / rho - h * h;
    float disc = fmaxf(B * B - 4.0f * A * C, 0.0f);
    hC   = (-B + sqrtf(disc)) / (2.0f * A);
    rhoC = 2.5f * pC / (hC - 1.0f);                   // gamma/(gamma-1) * pC/(hC-1)
    float j2   = fmaxf((pC - p) / (h / rho - hC / rhoC), 1e-12f);
    float jabs = sqrtf(j2);
    float rw   = rho * W;
    float a2   = rw * rw;
    Vs = (a2 * v + sign * jabs * sqrtf(j2 + a2 * (1.0f - v * v))) / (a2 + j2);
    float Ws = 1.0f / sqrtf(fmaxf(1.0f - Vs * Vs, 1e-12f));
    float js = sign * jabs;
    vstar = (h * W * v + Ws * (pC - p) / js) /
            (h * W + (pC - p) * (Ws * v / js + 1.0f / (rho * W)));
}

__global__ void __launch_bounds__(NTHREADS)
shock_solver_kernel(const float* __restrict__ P, const float* __restrict__ F,
                    const float* __restrict__ W1, const float* __restrict__ b1,
                    const float* __restrict__ W2, const float* __restrict__ b2,
                    const float* __restrict__ W3, const float* __restrict__ b3,
                    float* __restrict__ out, int N)
{
    extern __shared__ float smem[];

    // Stage all ensemble weights into shared memory once per CTA.
    for (int i = threadIdx.x; i < 3072;  i += NTHREADS) smem[OFF_W1 + i] = W1[i];
    for (int i = threadIdx.x; i < 512;   i += NTHREADS) smem[OFF_B1 + i] = b1[i];
    for (int i = threadIdx.x; i < 32768; i += NTHREADS) smem[OFF_W2 + i] = W2[i];
    for (int i = threadIdx.x; i < 512;   i += NTHREADS) smem[OFF_B2 + i] = b2[i];
    for (int i = threadIdx.x; i < 512;   i += NTHREADS) smem[OFF_W3 + i] = W3[i];
    for (int i = threadIdx.x; i < 8;     i += NTHREADS) smem[OFF_B3 + i] = b3[i];
    __syncthreads();

    const float* sW1 = smem + OFF_W1;
    const float* sB1 = smem + OFF_B1;
    const float* sW2 = smem + OFF_W2;
    const float* sB2 = smem + OFF_B2;
    const float* sW3 = smem + OFF_W3;
    const float* sB3 = smem + OFF_B3;

    const int stride = gridDim.x * NTHREADS;
    for (int n = blockIdx.x * NTHREADS + threadIdx.x; n < N; n += stride) {
        // P layout: (N, 3, 2) -> [rhoL, rhoR, pL, pR, vL, vR]
        const float rhoL = P[n * 6 + 0], rhoR = P[n * 6 + 1];
        const float pL   = P[n * 6 + 2], pR   = P[n * 6 + 3];
        const float vL   = P[n * 6 + 4], vR   = P[n * 6 + 5];

        float x[6];
        x[0] = logf(rhoL); x[1] = logf(rhoR);
        x[2] = logf(pL);   x[3] = logf(pR);
        x[4] = vL;         x[5] = vR;
        const float a = fmaxf(pL, pR);

        float bestdiff = 3.4e38f;
        float bestP    = 0.0f;

        for (int e = 0; e < NENS; e++) {
            const float* w1  = sW1 + e * (6 * HID);
            const float* bb1 = sB1 + e * HID;
            const float* w2  = sW2 + e * (HID * HID);
            const float* bb2 = sB2 + e * HID;
            const float* w3  = sW3 + e * HID;

            // Layer 1: h1 = tanh(x @ W1 + b1). Fully unrolled -> h1 in registers.
            float h1[HID];
            #pragma unroll
            for (int j = 0; j < HID; j += 4) {
                float4 b = *(const float4*)(bb1 + j);
                float s0 = b.x, s1 = b.y, s2 = b.z, s3 = b.w;
                #pragma unroll
                for (int i = 0; i < 6; i++) {
                    float4 w = *(const float4*)(w1 + i * HID + j);
                    float xv = x[i];
                    s0 = fmaf(xv, w.x, s0);
                    s1 = fmaf(xv, w.y, s1);
                    s2 = fmaf(xv, w.z, s2);
                    s3 = fmaf(xv, w.w, s3);
                }
                h1[j + 0] = tanhf(s0);
                h1[j + 1] = tanhf(s1);
                h1[j + 2] = tanhf(s2);
                h1[j + 3] = tanhf(s3);
            }

            // Layers 2+3 fused: z = sum_j tanh(h1 @ W2[:,j] + b2[j]) * W3[j] + b3
            float acc = sB3[e];
            for (int j = 0; j < HID; j += 4) {   // runtime loop (I-cache friendly)
                float4 b = *(const float4*)(bb2 + j);
                float s0 = b.x, s1 = b.y, s2 = b.z, s3 = b.w;
                #pragma unroll
                for (int k = 0; k < HID; k++) {  // full unroll: h1[k] compile-time
                    float4 w = *(const float4*)(w2 + k * HID + j);
                    float hk = h1[k];
                    s0 = fmaf(hk, w.x, s0);
                    s1 = fmaf(hk, w.y, s1);
                    s2 = fmaf(hk, w.z, s2);
                    s3 = fmaf(hk, w.w, s3);
                }
                float4 wv = *(const float4*)(w3 + j);
                acc += tanhf(s0) * wv.x + tanhf(s1) * wv.y
                     + tanhf(s2) * wv.z + tanhf(s3) * wv.w;
            }

            // xi = sigmoid(z); a*(1+xi)/(1-xi) == a*(1 + 2*exp(z))  (exact algebra)
            float pressC = a * (1.0f + 2.0f * expf(acc));

            float rC, hC, vsL, VsL, vsR, VsR;
            get_vel_shock(pressC, rhoL, pL, vL, -1.0f, rC, hC, vsL, VsL);
            get_vel_shock(pressC, rhoR, pR, vR,  1.0f, rC, hC, vsR, VsR);
            float d = fabsf(vsL - vsR);
            if (d < bestdiff) { bestdiff = d; bestP = pressC; }
        }

        // Recompute full shock state for the selected ensemble member.
        float rhoCL, hCL, vstarL, vshL;
        get_vel_shock(bestP, rhoL, pL, vL, -1.0f, rhoCL, hCL, vstarL, vshL);
        float rhoCR, hCR, vstarR, vshR;
        get_vel_shock(bestP, rhoR, pR, vR,  1.0f, rhoCR, hCR, vstarR, vshR);

        float lam = 0.5f * (vstarR + vstarL);
        float WC  = 1.0f / sqrtf(1.0f - lam * lam);
        float densCL = WC * rhoCL, densCR = WC * rhoCR;

        float f0 = 0.0f, f1 = 0.0f, f2 = 0.0f;
        // jnp.where chain: later masks override earlier ones.
        if (vshL >= 0.0f) {
            f0 = F[n * 6 + 0]; f1 = F[n * 6 + 2]; f2 = F[n * 6 + 4];
        }
        if (vshL < 0.0f && lam > 0.0f) {
            f0 = densCL * lam;
            f1 = densCL * (WC * hCL - 1.0f) * lam;
            f2 = (WC * WC * rhoCL * hCL * lam) * lam + bestP;
        }
        if (lam <= 0.0f && vshR > 0.0f) {
            f0 = densCR * lam;
            f1 = densCR * (WC * hCR - 1.0f) * lam;
            f2 = (WC * WC * rhoCR * hCR * lam) * lam + bestP;
        }
        if (vshR <= 0.0f) {
            f0 = F[n * 6 + 1]; f1 = F[n * 6 + 3]; f2 = F[n * 6 + 5];
        }

        out[n * 3 + 0] = f0;
        out[n * 3 + 1] = f1;
        out[n * 3 + 2] = f2;
    }
}

extern "C" void kernel_launch(void* const* d_in, const int* in_sizes, int n_in,
                              void* d_out, int out_size)
{
    // Input order (metadata): P, U, F, cmax, cmin, W1, b1, W2, b2, W3, b3
    const float* P  = (const float*)d_in[0];
    const float* F  = (const float*)d_in[2];
    const float* W1 = (const float*)d_in[5];
    const float* b1 = (const float*)d_in[6];
    const float* W2 = (const float*)d_in[7];
    const float* b2 = (const float*)d_in[8];
    const float* W3 = (const float*)d_in[9];
    const float* b3 = (const float*)d_in[10];
    float* out = (float*)d_out;
    const int N = in_sizes[0] / 6;

    cudaFuncSetAttribute(shock_solver_kernel,
                         cudaFuncAttributeMaxDynamicSharedMemorySize, SMEM_BYTES);

    shock_solver_kernel<<<148, NTHREADS, SMEM_BYTES>>>(
        P, F, W1, b1, W2, b2, W3, b3, out, N);
}

// round 2
// speedup vs baseline: 1.1346x; 1.1346x over previous
#include <cuda_runtime.h>
#include <math.h>
#include <stdint.h>

#define NTHREADS 256
#define NENS 8
#define HID 64

// Shared-memory float offsets (all 16B aligned)
#define OFF_W1 0                 // 8*6*64  = 3072
#define OFF_B1 3072              // 8*64    = 512
#define OFF_W2 3584              // 8*64*64 = 32768
#define OFF_B2 36352             // 512
#define OFF_W3 36864             // 512
#define OFF_B3 37376             // 8
#define SMEM_FLOATS 37384
#define SMEM_BYTES (SMEM_FLOATS * 4)

// ---- packed fp32x2 primitives (sm_103a FFMA2 — PTX-only, ptxas won't fuse) ----
#define FFMA2(d, a, b, c) \
    asm("fma.rn.f32x2 %0, %1, %2, %3;" : "=l"(d) : "l"(a), "l"(b), "l"(c))

__device__ __forceinline__ uint64_t pack2(float v) {
    uint64_t r;
    asm("mov.b64 %0, {%1, %1};" : "=l"(r) : "f"(v));
    return r;
}
__device__ __forceinline__ void unpack2(uint64_t s, float& lo, float& hi) {
    asm("mov.b64 {%0, %1}, %2;" : "=f"(lo), "=f"(hi) : "l"(s));
}

// ---- fast transcendentals: branch-free, MUFU-only, ~1e-6 rel err ----
__device__ __forceinline__ float fast_tanh(float x) {
    // tanh(x) = 1 - 2/(exp(2x)+1); saturates correctly (ex2->inf -> rcp->0 -> 1)
    float e, r;
    asm("ex2.approx.f32 %0, %1;" : "=f"(e) : "f"(x * 2.8853900817779268f)); // 2*log2(e)
    asm("rcp.approx.f32 %0, %1;" : "=f"(r) : "f"(e + 1.0f));
    return fmaf(-2.0f, r, 1.0f);
}
__device__ __forceinline__ float fast_exp(float x) {
    float e;
    asm("ex2.approx.f32 %0, %1;" : "=f"(e) : "f"(x * 1.4426950408889634f)); // log2(e)
    return e;
}

// Relativistic shock jump (Taub adiabat), gamma = 5/3.
__device__ __forceinline__ void get_vel_shock(
    float pC, float rho, float p, float v, float sign,
    float& rhoC, float& hC, float& vstar, float& Vs)
{
    float h  = 1.0f + 2.5f * p / rho;                 // gamma/(gamma-1) = 2.5
    float W  = 1.0f / sqrtf(1.0f - v * v);
    float dp = p - pC;
    float A  = 1.0f + 0.4f * dp / pC;                 // (gamma-1)/gamma = 0.4
    float B  = -0.4f * dp / pC;
    float C  = h * dp / rho - h * h;
    float disc = fmaxf(B * B - 4.0f * A * C, 0.0f);
    hC   = (-B + sqrtf(disc)) / (2.0f * A);
    rhoC = 2.5f * pC / (hC - 1.0f);
    float j2   = fmaxf((pC - p) / (h / rho - hC / rhoC), 1e-12f);
    float jabs = sqrtf(j2);
    float rw   = rho * W;
    float a2   = rw * rw;
    Vs = (a2 * v + sign * jabs * sqrtf(j2 + a2 * (1.0f - v * v))) / (a2 + j2);
    float Ws = 1.0f / sqrtf(fmaxf(1.0f - Vs * Vs, 1e-12f));
    float js = sign * jabs;
    vstar = (h * W * v + Ws * (pC - p) / js) /
            (h * W + (pC - p) * (Ws * v / js + 1.0f / (rho * W)));
}

__global__ void __launch_bounds__(NTHREADS)
shock_solver_kernel(const float* __restrict__ P, const float* __restrict__ F,
                    const float* __restrict__ W1, const float* __restrict__ b1,
                    const float* __restrict__ W2, const float* __restrict__ b2,
                    const float* __restrict__ W3, const float* __restrict__ b3,
                    float* __restrict__ out, int N)
{
    extern __shared__ float smem[];

    for (int i = threadIdx.x; i < 3072;  i += NTHREADS) smem[OFF_W1 + i] = W1[i];
    for (int i = threadIdx.x; i < 512;   i += NTHREADS) smem[OFF_B1 + i] = b1[i];
    for (int i = threadIdx.x; i < 32768; i += NTHREADS) smem[OFF_W2 + i] = W2[i];
    for (int i = threadIdx.x; i < 512;   i += NTHREADS) smem[OFF_B2 + i] = b2[i];
    for (int i = threadIdx.x; i < 512;   i += NTHREADS) smem[OFF_W3 + i] = W3[i];
    for (int i = threadIdx.x; i < 8;     i += NTHREADS) smem[OFF_B3 + i] = b3[i];
    __syncthreads();

    const float* sW1 = smem + OFF_W1;
    const float* sB1 = smem + OFF_B1;
    const float* sW2 = smem + OFF_W2;
    const float* sB2 = smem + OFF_B2;
    const float* sW3 = smem + OFF_W3;
    const float* sB3 = smem + OFF_B3;

    const int stride = gridDim.x * NTHREADS;
    for (int n = blockIdx.x * NTHREADS + threadIdx.x; n < N; n += stride) {
        const float rhoL = P[n * 6 + 0], rhoR = P[n * 6 + 1];
        const float pL   = P[n * 6 + 2], pR   = P[n * 6 + 3];
        const float vL   = P[n * 6 + 4], vR   = P[n * 6 + 5];

        // inputs duplicated into both f32x2 lanes (once per cell)
        uint64_t xd[6];
        xd[0] = pack2(logf(rhoL)); xd[1] = pack2(logf(rhoR));
        xd[2] = pack2(logf(pL));   xd[3] = pack2(logf(pR));
        xd[4] = pack2(vL);         xd[5] = pack2(vR);
        const float a = fmaxf(pL, pR);

        float bestdiff = 3.4e38f;
        float bestP    = 0.0f;

        for (int e = 0; e < NENS; e++) {
            const float* w1  = sW1 + e * (6 * HID);
            const float* bb1 = sB1 + e * HID;
            const float* w2  = sW2 + e * (HID * HID);
            const float* bb2 = sB2 + e * HID;
            const float* w3  = sW3 + e * HID;

            // ---- Layer 1: h1 = tanh(x @ W1 + b1), packed over j-pairs ----
            float h1[HID];
            #pragma unroll
            for (int j = 0; j < HID; j += 8) {
                ulonglong2 bA = *(const ulonglong2*)(bb1 + j);
                ulonglong2 bB = *(const ulonglong2*)(bb1 + j + 4);
                uint64_t s0 = bA.x, s1 = bA.y, s2 = bB.x, s3 = bB.y;
                #pragma unroll
                for (int i = 0; i < 6; i++) {
                    ulonglong2 wA = *(const ulonglong2*)(w1 + i * HID + j);
                    ulonglong2 wB = *(const ulonglong2*)(w1 + i * HID + j + 4);
                    FFMA2(s0, xd[i], wA.x, s0);
                    FFMA2(s1, xd[i], wA.y, s1);
                    FFMA2(s2, xd[i], wB.x, s2);
                    FFMA2(s3, xd[i], wB.y, s3);
                }
                float u0, u1, u2, u3, u4, u5, u6, u7;
                unpack2(s0, u0, u1); unpack2(s1, u2, u3);
                unpack2(s2, u4, u5); unpack2(s3, u6, u7);
                h1[j + 0] = fast_tanh(u0); h1[j + 1] = fast_tanh(u1);
                h1[j + 2] = fast_tanh(u2); h1[j + 3] = fast_tanh(u3);
                h1[j + 4] = fast_tanh(u4); h1[j + 5] = fast_tanh(u5);
                h1[j + 6] = fast_tanh(u6); h1[j + 7] = fast_tanh(u7);
            }

            // ---- Layers 2+3 fused, packed over j-pairs ----
            float acc = sB3[e];
            for (int j = 0; j < HID; j += 8) {   // runtime loop (I-cache)
                ulonglong2 bA = *(const ulonglong2*)(bb2 + j);
                ulonglong2 bB = *(const ulonglong2*)(bb2 + j + 4);
                uint64_t s0 = bA.x, s1 = bA.y, s2 = bB.x, s3 = bB.y;
                #pragma unroll
                for (int k = 0; k < HID; k++) {
                    uint64_t hk = pack2(h1[k]);
                    ulonglong2 wA = *(const ulonglong2*)(w2 + k * HID + j);
                    ulonglong2 wB = *(const ulonglong2*)(w2 + k * HID + j + 4);
                    FFMA2(s0, hk, wA.x, s0);
                    FFMA2(s1, hk, wA.y, s1);
                    FFMA2(s2, hk, wB.x, s2);
                    FFMA2(s3, hk, wB.y, s3);
                }
                float u0, u1, u2, u3, u4, u5, u6, u7;
                unpack2(s0, u0, u1); unpack2(s1, u2, u3);
                unpack2(s2, u4, u5); unpack2(s3, u6, u7);
                float4 wvA = *(const float4*)(w3 + j);
                float4 wvB = *(const float4*)(w3 + j + 4);
                acc += fast_tanh(u0) * wvA.x + fast_tanh(u1) * wvA.y
                     + fast_tanh(u2) * wvA.z + fast_tanh(u3) * wvA.w
                     + fast_tanh(u4) * wvB.x + fast_tanh(u5) * wvB.y
                     + fast_tanh(u6) * wvB.z + fast_tanh(u7) * wvB.w;
            }

            // xi = sigmoid(z); a*(1+xi)/(1-xi) == a*(1 + 2*exp(z))
            float pressC = a * (1.0f + 2.0f * fast_exp(acc));

            float rC, hC, vsL, VsL, vsR, VsR;
            get_vel_shock(pressC, rhoL, pL, vL, -1.0f, rC, hC, vsL, VsL);
            get_vel_shock(pressC, rhoR, pR, vR,  1.0f, rC, hC, vsR, VsR);
            float d = fabsf(vsL - vsR);
            if (d < bestdiff) { bestdiff = d; bestP = pressC; }
        }

        // Recompute full shock state for the selected ensemble member.
        float rhoCL, hCL, vstarL, vshL;
        get_vel_shock(bestP, rhoL, pL, vL, -1.0f, rhoCL, hCL, vstarL, vshL);
        float rhoCR, hCR, vstarR, vshR;
        get_vel_shock(bestP, rhoR, pR, vR,  1.0f, rhoCR, hCR, vstarR, vshR);

        float lam = 0.5f * (vstarR + vstarL);
        float WC  = 1.0f / sqrtf(1.0f - lam * lam);
        float densCL = WC * rhoCL, densCR = WC * rhoCR;

        float f0 = 0.0f, f1 = 0.0f, f2 = 0.0f;
        if (vshL >= 0.0f) {
            f0 = F[n * 6 + 0]; f1 = F[n * 6 + 2]; f2 = F[n * 6 + 4];
        }
        if (vshL < 0.0f && lam > 0.0f) {
            f0 = densCL * lam;
            f1 = densCL * (WC * hCL - 1.0f) * lam;
            f2 = (WC * WC * rhoCL * hCL * lam) * lam + bestP;
        }
        if (lam <= 0.0f && vshR > 0.0f) {
            f0 = densCR * lam;
            f1 = densCR * (WC * hCR - 1.0f) * lam;
            f2 = (WC * WC * rhoCR * hCR * lam) * lam + bestP;
        }
        if (vshR <= 0.0f) {
            f0 = F[n * 6 + 1]; f1 = F[n * 6 + 3]; f2 = F[n * 6 + 5];
        }

        out[n * 3 + 0] = f0;
        out[n * 3 + 1] = f1;
        out[n * 3 + 2] = f2;
    }
}

extern "C" void kernel_launch(void* const* d_in, const int* in_sizes, int n_in,
                              void* d_out, int out_size)
{
    const float* P  = (const float*)d_in[0];
    const float* F  = (const float*)d_in[2];
    const float* W1 = (const float*)d_in[5];
    const float* b1 = (const float*)d_in[6];
    const float* W2 = (const float*)d_in[7];
    const float* b2 = (const float*)d_in[8];
    const float* W3 = (const float*)d_in[9];
    const float* b3 = (const float*)d_in[10];
    float* out = (float*)d_out;
    const int N = in_sizes[0] / 6;

    cudaFuncSetAttribute(shock_solver_kernel,
                         cudaFuncAttributeMaxDynamicSharedMemorySize, SMEM_BYTES);

    shock_solver_kernel<<<148, NTHREADS, SMEM_BYTES>>>(
        P, F, W1, b1, W2, b2, W3, b3, out, N);
}

// round 3
// speedup vs baseline: 1.2225x; 1.0775x over previous
#include <cuda_runtime.h>
#include <math.h>
#include <stdint.h>

#define NTHREADS 512
#define NENS 8
#define HID 64

// Shared-memory float offsets (all 16B aligned)
#define OFF_W1 0                 // 8*6*64  = 3072
#define OFF_B1 3072              // 8*64    = 512
#define OFF_W2 3584              // 8*64*64 = 32768
#define OFF_B2 36352             // 512
#define OFF_W3 36864             // 512
#define OFF_B3 37376             // 8
#define SMEM_FLOATS 37384
#define SMEM_BYTES (SMEM_FLOATS * 4)

// ---- packed fp32x2 primitives (sm_103a FFMA2 — PTX-only, ptxas won't fuse) ----
#define FFMA2(d, a, b, c) \
    asm("fma.rn.f32x2 %0, %1, %2, %3;" : "=l"(d) : "l"(a), "l"(b), "l"(c))

__device__ __forceinline__ uint64_t pack2(float v) {
    uint64_t r;
    asm("mov.b64 %0, {%1, %1};" : "=l"(r) : "f"(v));
    return r;
}
__device__ __forceinline__ void unpack2(uint64_t s, float& lo, float& hi) {
    asm("mov.b64 {%0, %1}, %2;" : "=f"(lo), "=f"(hi) : "l"(s));
}

// ---- fast transcendentals: branch-free, MUFU-only, ~1e-6 rel err ----
__device__ __forceinline__ float fast_tanh(float x) {
    // tanh(x) = 1 - 2/(exp(2x)+1); saturates correctly (ex2->inf -> rcp->0 -> 1)
    float e, r;
    asm("ex2.approx.f32 %0, %1;" : "=f"(e) : "f"(x * 2.8853900817779268f)); // 2*log2(e)
    asm("rcp.approx.f32 %0, %1;" : "=f"(r) : "f"(e + 1.0f));
    return fmaf(-2.0f, r, 1.0f);
}
__device__ __forceinline__ float fast_exp(float x) {
    float e;
    asm("ex2.approx.f32 %0, %1;" : "=f"(e) : "f"(x * 1.4426950408889634f)); // log2(e)
    return e;
}

// Relativistic shock jump (Taub adiabat), gamma = 5/3.
__device__ __forceinline__ void get_vel_shock(
    float pC, float rho, float p, float v, float sign,
    float& rhoC, float& hC, float& vstar, float& Vs)
{
    float h  = 1.0f + 2.5f * p / rho;                 // gamma/(gamma-1) = 2.5
    float W  = 1.0f / sqrtf(1.0f - v * v);
    float dp = p - pC;
    float A  = 1.0f + 0.4f * dp / pC;                 // (gamma-1)/gamma = 0.4
    float B  = -0.4f * dp / pC;
    float C  = h * dp / rho - h * h;
    float disc = fmaxf(B * B - 4.0f * A * C, 0.0f);
    hC   = (-B + sqrtf(disc)) / (2.0f * A);
    rhoC = 2.5f * pC / (hC - 1.0f);
    float j2   = fmaxf((pC - p) / (h / rho - hC / rhoC), 1e-12f);
    float jabs = sqrtf(j2);
    float rw   = rho * W;
    float a2   = rw * rw;
    Vs = (a2 * v + sign * jabs * sqrtf(j2 + a2 * (1.0f - v * v))) / (a2 + j2);
    float Ws = 1.0f / sqrtf(fmaxf(1.0f - Vs * Vs, 1e-12f));
    float js = sign * jabs;
    vstar = (h * W * v + Ws * (pC - p) / js) /
            (h * W + (pC - p) * (Ws * v / js + 1.0f / (rho * W)));
}

__global__ void __launch_bounds__(NTHREADS)
shock_solver_kernel(const float* __restrict__ P, const float* __restrict__ F,
                    const float* __restrict__ W1, const float* __restrict__ b1,
                    const float* __restrict__ W2, const float* __restrict__ b2,
                    const float* __restrict__ W3, const float* __restrict__ b3,
                    float* __restrict__ out, int N)
{
    extern __shared__ float smem[];

    for (int i = threadIdx.x; i < 3072;  i += NTHREADS) smem[OFF_W1 + i] = W1[i];
    for (int i = threadIdx.x; i < 512;   i += NTHREADS) smem[OFF_B1 + i] = b1[i];
    for (int i = threadIdx.x; i < 32768; i += NTHREADS) smem[OFF_W2 + i] = W2[i];
    for (int i = threadIdx.x; i < 512;   i += NTHREADS) smem[OFF_B2 + i] = b2[i];
    for (int i = threadIdx.x; i < 512;   i += NTHREADS) smem[OFF_W3 + i] = W3[i];
    for (int i = threadIdx.x; i < 8;     i += NTHREADS) smem[OFF_B3 + i] = b3[i];
    __syncthreads();

    const float* sW1 = smem + OFF_W1;
    const float* sB1 = smem + OFF_B1;
    const float* sW2 = smem + OFF_W2;
    const float* sB2 = smem + OFF_B2;
    const float* sW3 = smem + OFF_W3;
    const float* sB3 = smem + OFF_B3;

    const int stride = gridDim.x * NTHREADS;
    for (int n = blockIdx.x * NTHREADS + threadIdx.x; n < N; n += stride) {
        const float rhoL = P[n * 6 + 0], rhoR = P[n * 6 + 1];
        const float pL   = P[n * 6 + 2], pR   = P[n * 6 + 3];
        const float vL   = P[n * 6 + 4], vR   = P[n * 6 + 5];

        // inputs duplicated into both f32x2 lanes (once per cell)
        uint64_t xd[6];
        xd[0] = pack2(logf(rhoL)); xd[1] = pack2(logf(rhoR));
        xd[2] = pack2(logf(pL));   xd[3] = pack2(logf(pR));
        xd[4] = pack2(vL);         xd[5] = pack2(vR);
        const float a = fmaxf(pL, pR);

        float bestdiff = 3.4e38f;
        float bestP    = 0.0f;

        for (int e = 0; e < NENS; e++) {
            const float* w1  = sW1 + e * (6 * HID);
            const float* bb1 = sB1 + e * HID;
            const float* w2  = sW2 + e * (HID * HID);
            const float* bb2 = sB2 + e * HID;
            const float* w3  = sW3 + e * HID;

            // ---- Layer 1: h1 = tanh(x @ W1 + b1), packed over j-pairs ----
            float h1[HID];
            #pragma unroll
            for (int j = 0; j < HID; j += 8) {
                ulonglong2 bA = *(const ulonglong2*)(bb1 + j);
                ulonglong2 bB = *(const ulonglong2*)(bb1 + j + 4);
                uint64_t s0 = bA.x, s1 = bA.y, s2 = bB.x, s3 = bB.y;
                #pragma unroll
                for (int i = 0; i < 6; i++) {
                    ulonglong2 wA = *(const ulonglong2*)(w1 + i * HID + j);
                    ulonglong2 wB = *(const ulonglong2*)(w1 + i * HID + j + 4);
                    FFMA2(s0, xd[i], wA.x, s0);
                    FFMA2(s1, xd[i], wA.y, s1);
                    FFMA2(s2, xd[i], wB.x, s2);
                    FFMA2(s3, xd[i], wB.y, s3);
                }
                float u0, u1, u2, u3, u4, u5, u6, u7;
                unpack2(s0, u0, u1); unpack2(s1, u2, u3);
                unpack2(s2, u4, u5); unpack2(s3, u6, u7);
                h1[j + 0] = fast_tanh(u0); h1[j + 1] = fast_tanh(u1);
                h1[j + 2] = fast_tanh(u2); h1[j + 3] = fast_tanh(u3);
                h1[j + 4] = fast_tanh(u4); h1[j + 5] = fast_tanh(u5);
                h1[j + 6] = fast_tanh(u6); h1[j + 7] = fast_tanh(u7);
            }

            // ---- Layers 2+3 fused, packed over j-pairs ----
            float acc = sB3[e];
            for (int j = 0; j < HID; j += 8) {   // runtime loop (I-cache)
                ulonglong2 bA = *(const ulonglong2*)(bb2 + j);
                ulonglong2 bB = *(const ulonglong2*)(bb2 + j + 4);
                uint64_t s0 = bA.x, s1 = bA.y, s2 = bB.x, s3 = bB.y;
                #pragma unroll
                for (int k = 0; k < HID; k++) {
                    uint64_t hk = pack2(h1[k]);
                    ulonglong2 wA = *(const ulonglong2*)(w2 + k * HID + j);
                    ulonglong2 wB = *(const ulonglong2*)(w2 + k * HID + j + 4);
                    FFMA2(s0, hk, wA.x, s0);
                    FFMA2(s1, hk, wA.y, s1);
                    FFMA2(s2, hk, wB.x, s2);
                    FFMA2(s3, hk, wB.y, s3);
                }
                float u0, u1, u2, u3, u4, u5, u6, u7;
                unpack2(s0, u0, u1); unpack2(s1, u2, u3);
                unpack2(s2, u4, u5); unpack2(s3, u6, u7);
                float4 wvA = *(const float4*)(w3 + j);
                float4 wvB = *(const float4*)(w3 + j + 4);
                acc += fast_tanh(u0) * wvA.x + fast_tanh(u1) * wvA.y
                     + fast_tanh(u2) * wvA.z + fast_tanh(u3) * wvA.w
                     + fast_tanh(u4) * wvB.x + fast_tanh(u5) * wvB.y
                     + fast_tanh(u6) * wvB.z + fast_tanh(u7) * wvB.w;
            }

            // xi = sigmoid(z); a*(1+xi)/(1-xi) == a*(1 + 2*exp(z))
            float pressC = a * (1.0f + 2.0f * fast_exp(acc));

            float rC, hC, vsL, VsL, vsR, VsR;
            get_vel_shock(pressC, rhoL, pL, vL, -1.0f, rC, hC, vsL, VsL);
            get_vel_shock(pressC, rhoR, pR, vR,  1.0f, rC, hC, vsR, VsR);
            float d = fabsf(vsL - vsR);
            if (d < bestdiff) { bestdiff = d; bestP = pressC; }
        }

        // Recompute full shock state for the selected ensemble member.
        float rhoCL, hCL, vstarL, vshL;
        get_vel_shock(bestP, rhoL, pL, vL, -1.0f, rhoCL, hCL, vstarL, vshL);
        float rhoCR, hCR, vstarR, vshR;
        get_vel_shock(bestP, rhoR, pR, vR,  1.0f, rhoCR, hCR, vstarR, vshR);

        float lam = 0.5f * (vstarR + vstarL);
        float WC  = 1.0f / sqrtf(1.0f - lam * lam);
        float densCL = WC * rhoCL, densCR = WC * rhoCR;

        float f0 = 0.0f, f1 = 0.0f, f2 = 0.0f;
        if (vshL >= 0.0f) {
            f0 = F[n * 6 + 0]; f1 = F[n * 6 + 2]; f2 = F[n * 6 + 4];
        }
        if (vshL < 0.0f && lam > 0.0f) {
            f0 = densCL * lam;
            f1 = densCL * (WC * hCL - 1.0f) * lam;
            f2 = (WC * WC * rhoCL * hCL * lam) * lam + bestP;
        }
        if (lam <= 0.0f && vshR > 0.0f) {
            f0 = densCR * lam;
            f1 = densCR * (WC * hCR - 1.0f) * lam;
            f2 = (WC * WC * rhoCR * hCR * lam) * lam + bestP;
        }
        if (vshR <= 0.0f) {
            f0 = F[n * 6 + 1]; f1 = F[n * 6 + 3]; f2 = F[n * 6 + 5];
        }

        out[n * 3 + 0] = f0;
        out[n * 3 + 1] = f1;
        out[n * 3 + 2] = f2;
    }
}

extern "C" void kernel_launch(void* const* d_in, const int* in_sizes, int n_in,
                              void* d_out, int out_size)
{
    const float* P  = (const float*)d_in[0];
    const float* F  = (const float*)d_in[2];
    const float* W1 = (const float*)d_in[5];
    const float* b1 = (const float*)d_in[6];
    const float* W2 = (const float*)d_in[7];
    const float* b2 = (const float*)d_in[8];
    const float* W3 = (const float*)d_in[9];
    const float* b3 = (const float*)d_in[10];
    float* out = (float*)d_out;
    const int N = in_sizes[0] / 6;

    cudaFuncSetAttribute(shock_solver_kernel,
                         cudaFuncAttributeMaxDynamicSharedMemorySize, SMEM_BYTES);

    shock_solver_kernel<<<148, NTHREADS, SMEM_BYTES>>>(
        P, F, W1, b1, W2, b2, W3, b3, out, N);
}

// round 4
// speedup vs baseline: 1.3315x; 1.0892x over previous
#include <cuda_runtime.h>
#include <math.h>
#include <stdint.h>

#define NTHREADS 256
#define NENS 8
#define HID 64

// Shared-memory float offsets (all 16B aligned)
#define OFF_W1 0                 // 8*6*64  = 3072
#define OFF_B1 3072              // 8*64    = 512
#define OFF_W2 3584              // 8*64*64 = 32768
#define OFF_B2 36352             // 512
#define OFF_W3 36864             // 512
#define OFF_B3 37376             // 8
#define SMEM_FLOATS 37384
#define SMEM_BYTES (SMEM_FLOATS * 4)

// ---- packed fp32x2 primitives (sm_103a FFMA2 — PTX-only) ----
#define FFMA2(d, a, b, c) \
    asm("fma.rn.f32x2 %0, %1, %2, %3;" : "=l"(d) : "l"(a), "l"(b), "l"(c))

__device__ __forceinline__ uint64_t pack2(float v) {
    uint64_t r;
    asm("mov.b64 %0, {%1, %1};" : "=l"(r) : "f"(v));
    return r;
}
__device__ __forceinline__ void unpack2(uint64_t s, float& lo, float& hi) {
    asm("mov.b64 {%0, %1}, %2;" : "=f"(lo), "=f"(hi) : "l"(s));
}

// ---- fast transcendentals: branch-free, MUFU-only, ~1e-6 rel err ----
__device__ __forceinline__ float fast_tanh(float x) {
    float e, r;
    asm("ex2.approx.f32 %0, %1;" : "=f"(e) : "f"(x * 2.8853900817779268f)); // 2*log2(e)
    asm("rcp.approx.f32 %0, %1;" : "=f"(r) : "f"(e + 1.0f));
    return fmaf(-2.0f, r, 1.0f);
}
__device__ __forceinline__ float fast_exp(float x) {
    float e;
    asm("ex2.approx.f32 %0, %1;" : "=f"(e) : "f"(x * 1.4426950408889634f)); // log2(e)
    return e;
}

// Relativistic shock jump (Taub adiabat), gamma = 5/3.
__device__ __forceinline__ void get_vel_shock(
    float pC, float rho, float p, float v, float sign,
    float& rhoC, float& hC, float& vstar, float& Vs)
{
    float h  = 1.0f + 2.5f * p / rho;
    float W  = 1.0f / sqrtf(1.0f - v * v);
    float dp = p - pC;
    float A  = 1.0f + 0.4f * dp / pC;
    float B  = -0.4f * dp / pC;
    float C  = h * dp / rho - h * h;
    float disc = fmaxf(B * B - 4.0f * A * C, 0.0f);
    hC   = (-B + sqrtf(disc)) / (2.0f * A);
    rhoC = 2.5f * pC / (hC - 1.0f);
    float j2   = fmaxf((pC - p) / (h / rho - hC / rhoC), 1e-12f);
    float jabs = sqrtf(j2);
    float rw   = rho * W;
    float a2   = rw * rw;
    Vs = (a2 * v + sign * jabs * sqrtf(j2 + a2 * (1.0f - v * v))) / (a2 + j2);
    float Ws = 1.0f / sqrtf(fmaxf(1.0f - Vs * Vs, 1e-12f));
    float js = sign * jabs;
    vstar = (h * W * v + Ws * (pC - p) / js) /
            (h * W + (pC - p) * (Ws * v / js + 1.0f / (rho * W)));
}

// Flux selection (jnp.where chain, later masks override earlier)
__device__ __forceinline__ void finish_cell(
    const float* __restrict__ F, float* __restrict__ out, int n,
    float bestP, float rho_l, float p_l, float v_l,
    float rho_r, float p_r, float v_r)
{
    float rhoCL, hCL, vstarL, vshL;
    get_vel_shock(bestP, rho_l, p_l, v_l, -1.0f, rhoCL, hCL, vstarL, vshL);
    float rhoCR, hCR, vstarR, vshR;
    get_vel_shock(bestP, rho_r, p_r, v_r,  1.0f, rhoCR, hCR, vstarR, vshR);

    float lam = 0.5f * (vstarR + vstarL);
    float WC  = 1.0f / sqrtf(1.0f - lam * lam);
    float densCL = WC * rhoCL, densCR = WC * rhoCR;

    float f0 = 0.0f, f1 = 0.0f, f2 = 0.0f;
    if (vshL >= 0.0f) {
        f0 = F[n * 6 + 0]; f1 = F[n * 6 + 2]; f2 = F[n * 6 + 4];
    }
    if (vshL < 0.0f && lam > 0.0f) {
        f0 = densCL * lam;
        f1 = densCL * (WC * hCL - 1.0f) * lam;
        f2 = (WC * WC * rhoCL * hCL * lam) * lam + bestP;
    }
    if (lam <= 0.0f && vshR > 0.0f) {
        f0 = densCR * lam;
        f1 = densCR * (WC * hCR - 1.0f) * lam;
        f2 = (WC * WC * rhoCR * hCR * lam) * lam + bestP;
    }
    if (vshR <= 0.0f) {
        f0 = F[n * 6 + 1]; f1 = F[n * 6 + 3]; f2 = F[n * 6 + 5];
    }
    out[n * 3 + 0] = f0;
    out[n * 3 + 1] = f1;
    out[n * 3 + 2] = f2;
}

__global__ void __launch_bounds__(NTHREADS)
shock_solver_kernel(const float* __restrict__ P, const float* __restrict__ F,
                    const float* __restrict__ W1, const float* __restrict__ b1,
                    const float* __restrict__ W2, const float* __restrict__ b2,
                    const float* __restrict__ W3, const float* __restrict__ b3,
                    float* __restrict__ out, int N)
{
    extern __shared__ float smem[];

    for (int i = threadIdx.x; i < 3072;  i += NTHREADS) smem[OFF_W1 + i] = W1[i];
    for (int i = threadIdx.x; i < 512;   i += NTHREADS) smem[OFF_B1 + i] = b1[i];
    for (int i = threadIdx.x; i < 32768; i += NTHREADS) smem[OFF_W2 + i] = W2[i];
    for (int i = threadIdx.x; i < 512;   i += NTHREADS) smem[OFF_B2 + i] = b2[i];
    for (int i = threadIdx.x; i < 512;   i += NTHREADS) smem[OFF_W3 + i] = W3[i];
    for (int i = threadIdx.x; i < 8;     i += NTHREADS) smem[OFF_B3 + i] = b3[i];
    __syncthreads();

    const float* sW1 = smem + OFF_W1;
    const float* sB1 = smem + OFF_B1;
    const float* sW2 = smem + OFF_W2;
    const float* sB2 = smem + OFF_B2;
    const float* sW3 = smem + OFF_W3;
    const float* sB3 = smem + OFF_B3;

    const int stride2 = gridDim.x * NTHREADS * 2;
    for (int n = (blockIdx.x * NTHREADS + threadIdx.x) * 2; n < N; n += stride2) {
        const int nb = n + 1;              // second cell (N = 1e6 is even; guarded anyway)
        const bool has_b = (nb < N);
        const int nb_s = has_b ? nb : n;   // safe index for loads

        // Cell A primitives
        const float rhoLa = P[n * 6 + 0], rhoRa = P[n * 6 + 1];
        const float pLa   = P[n * 6 + 2], pRa   = P[n * 6 + 3];
        const float vLa   = P[n * 6 + 4], vRa   = P[n * 6 + 5];
        // Cell B primitives
        const float rhoLb = P[nb_s * 6 + 0], rhoRb = P[nb_s * 6 + 1];
        const float pLb   = P[nb_s * 6 + 2], pRb   = P[nb_s * 6 + 3];
        const float vLb   = P[nb_s * 6 + 4], vRb   = P[nb_s * 6 + 5];

        uint64_t xa[6], xb[6];
        xa[0] = pack2(logf(rhoLa)); xa[1] = pack2(logf(rhoRa));
        xa[2] = pack2(logf(pLa));   xa[3] = pack2(logf(pRa));
        xa[4] = pack2(vLa);         xa[5] = pack2(vRa);
        xb[0] = pack2(logf(rhoLb)); xb[1] = pack2(logf(rhoRb));
        xb[2] = pack2(logf(pLb));   xb[3] = pack2(logf(pRb));
        xb[4] = pack2(vLb);         xb[5] = pack2(vRb);
        const float aa = fmaxf(pLa, pRa);
        const float ab = fmaxf(pLb, pRb);

        float bestdiff_a = 3.4e38f, bestP_a = 0.0f;
        float bestdiff_b = 3.4e38f, bestP_b = 0.0f;

        for (int e = 0; e < NENS; e++) {
            const float* w1  = sW1 + e * (6 * HID);
            const float* bb1 = sB1 + e * HID;
            const float* w2  = sW2 + e * (HID * HID);
            const float* bb2 = sB2 + e * HID;
            const float* w3  = sW3 + e * HID;

            // ---- Layer 1: both cells share each weight load ----
            float h1a[HID], h1b[HID];
            #pragma unroll
            for (int j = 0; j < HID; j += 8) {
                ulonglong2 bA = *(const ulonglong2*)(bb1 + j);
                ulonglong2 bB = *(const ulonglong2*)(bb1 + j + 4);
                uint64_t sa0 = bA.x, sa1 = bA.y, sa2 = bB.x, sa3 = bB.y;
                uint64_t sb0 = bA.x, sb1 = bA.y, sb2 = bB.x, sb3 = bB.y;
                #pragma unroll
                for (int i = 0; i < 6; i++) {
                    ulonglong2 wA = *(const ulonglong2*)(w1 + i * HID + j);
                    ulonglong2 wB = *(const ulonglong2*)(w1 + i * HID + j + 4);
                    FFMA2(sa0, xa[i], wA.x, sa0);  FFMA2(sb0, xb[i], wA.x, sb0);
                    FFMA2(sa1, xa[i], wA.y, sa1);  FFMA2(sb1, xb[i], wA.y, sb1);
                    FFMA2(sa2, xa[i], wB.x, sa2);  FFMA2(sb2, xb[i], wB.x, sb2);
                    FFMA2(sa3, xa[i], wB.y, sa3);  FFMA2(sb3, xb[i], wB.y, sb3);
                }
                float u0, u1, u2, u3, u4, u5, u6, u7;
                unpack2(sa0, u0, u1); unpack2(sa1, u2, u3);
                unpack2(sa2, u4, u5); unpack2(sa3, u6, u7);
                h1a[j + 0] = fast_tanh(u0); h1a[j + 1] = fast_tanh(u1);
                h1a[j + 2] = fast_tanh(u2); h1a[j + 3] = fast_tanh(u3);
                h1a[j + 4] = fast_tanh(u4); h1a[j + 5] = fast_tanh(u5);
                h1a[j + 6] = fast_tanh(u6); h1a[j + 7] = fast_tanh(u7);
                unpack2(sb0, u0, u1); unpack2(sb1, u2, u3);
                unpack2(sb2, u4, u5); unpack2(sb3, u6, u7);
                h1b[j + 0] = fast_tanh(u0); h1b[j + 1] = fast_tanh(u1);
                h1b[j + 2] = fast_tanh(u2); h1b[j + 3] = fast_tanh(u3);
                h1b[j + 4] = fast_tanh(u4); h1b[j + 5] = fast_tanh(u5);
                h1b[j + 6] = fast_tanh(u6); h1b[j + 7] = fast_tanh(u7);
            }

            // ---- Layers 2+3 fused: each LDS.128 feeds 8 FFMA2 (2 cells) ----
            float acca = sB3[e];
            float accb = acca;
            for (int j = 0; j < HID; j += 8) {   // runtime loop (I-cache)
                ulonglong2 bA = *(const ulonglong2*)(bb2 + j);
                ulonglong2 bB = *(const ulonglong2*)(bb2 + j + 4);
                uint64_t sa0 = bA.x, sa1 = bA.y, sa2 = bB.x, sa3 = bB.y;
                uint64_t sb0 = bA.x, sb1 = bA.y, sb2 = bB.x, sb3 = bB.y;
                #pragma unroll
                for (int k = 0; k < HID; k++) {
                    uint64_t ha = pack2(h1a[k]);
                    uint64_t hb = pack2(h1b[k]);
                    ulonglong2 wA = *(const ulonglong2*)(w2 + k * HID + j);
                    ulonglong2 wB = *(const ulonglong2*)(w2 + k * HID + j + 4);
                    FFMA2(sa0, ha, wA.x, sa0);  FFMA2(sb0, hb, wA.x, sb0);
                    FFMA2(sa1, ha, wA.y, sa1);  FFMA2(sb1, hb, wA.y, sb1);
                    FFMA2(sa2, ha, wB.x, sa2);  FFMA2(sb2, hb, wB.x, sb2);
                    FFMA2(sa3, ha, wB.y, sa3);  FFMA2(sb3, hb, wB.y, sb3);
                }
                float4 wvA = *(const float4*)(w3 + j);
                float4 wvB = *(const float4*)(w3 + j + 4);
                float u0, u1, u2, u3, u4, u5, u6, u7;
                unpack2(sa0, u0, u1); unpack2(sa1, u2, u3);
                unpack2(sa2, u4, u5); unpack2(sa3, u6, u7);
                acca += fast_tanh(u0) * wvA.x + fast_tanh(u1) * wvA.y
                      + fast_tanh(u2) * wvA.z + fast_tanh(u3) * wvA.w
                      + fast_tanh(u4) * wvB.x + fast_tanh(u5) * wvB.y
                      + fast_tanh(u6) * wvB.z + fast_tanh(u7) * wvB.w;
                unpack2(sb0, u0, u1); unpack2(sb1, u2, u3);
                unpack2(sb2, u4, u5); unpack2(sb3, u6, u7);
                accb += fast_tanh(u0) * wvA.x + fast_tanh(u1) * wvA.y
                      + fast_tanh(u2) * wvA.z + fast_tanh(u3) * wvA.w
                      + fast_tanh(u4) * wvB.x + fast_tanh(u5) * wvB.y
                      + fast_tanh(u6) * wvB.z + fast_tanh(u7) * wvB.w;
            }

            // pressC = a*(1 + 2*exp(z))  [== a*(1+sigmoid)/(1-sigmoid)]
            float pca = aa * (1.0f + 2.0f * fast_exp(acca));
            float pcb = ab * (1.0f + 2.0f * fast_exp(accb));

            float rC, hC, VsL, VsR, vsLa, vsRa, vsLb, vsRb;
            get_vel_shock(pca, rhoLa, pLa, vLa, -1.0f, rC, hC, vsLa, VsL);
            get_vel_shock(pca, rhoRa, pRa, vRa,  1.0f, rC, hC, vsRa, VsR);
            float da = fabsf(vsLa - vsRa);
            if (da < bestdiff_a) { bestdiff_a = da; bestP_a = pca; }

            get_vel_shock(pcb, rhoLb, pLb, vLb, -1.0f, rC, hC, vsLb, VsL);
            get_vel_shock(pcb, rhoRb, pRb, vRb,  1.0f, rC, hC, vsRb, VsR);
            float db = fabsf(vsLb - vsRb);
            if (db < bestdiff_b) { bestdiff_b = db; bestP_b = pcb; }
        }

        finish_cell(F, out, n, bestP_a, rhoLa, pLa, vLa, rhoRa, pRa, vRa);
        if (has_b)
            finish_cell(F, out, nb, bestP_b, rhoLb, pLb, vLb, rhoRb, pRb, vRb);
    }
}

extern "C" void kernel_launch(void* const* d_in, const int* in_sizes, int n_in,
                              void* d_out, int out_size)
{
    const float* P  = (const float*)d_in[0];
    const float* F  = (const float*)d_in[2];
    const float* W1 = (const float*)d_in[5];
    const float* b1 = (const float*)d_in[6];
    const float* W2 = (const float*)d_in[7];
    const float* b2 = (const float*)d_in[8];
    const float* W3 = (const float*)d_in[9];
    const float* b3 = (const float*)d_in[10];
    float* out = (float*)d_out;
    const int N = in_sizes[0] / 6;

    cudaFuncSetAttribute(shock_solver_kernel,
                         cudaFuncAttributeMaxDynamicSharedMemorySize, SMEM_BYTES);

    shock_solver_kernel<<<148, NTHREADS, SMEM_BYTES>>>(
        P, F, W1, b1, W2, b2, W3, b3, out, N);
}